// round 3
// baseline (speedup 1.0000x reference)
#include <cuda_runtime.h>
#include <math.h>

#define HH 512
#define WW 512
#define BB 16
#define IMG (HH*WW)            // 262144 = 1<<18
#define TOT (BB*IMG)           // 4194304
#define NTILES 4096            // 16 x-tiles * 16 y-tiles * 16 images
#define MAXR1 32
#define MAXR2 32
#define MAXR3 24
#define NFLAGS (MAXR1+MAXR2+MAXR3)
#define NEG (-INFINITY)

// Scratch (static __device__ arrays: allocation-free)
__device__ float g_m  [TOT];
__device__ float g_m2 [TOT];
__device__ float g_rmx[TOT];
__device__ float g_m3 [TOT];
__device__ unsigned char g_dirty[2][NTILES];
__device__ int   g_chflag[NFLAGS];
__device__ int   g_rflags[2];          // [0]: any Rmax==0, [1]: any Rmax==1
__device__ float g_cc[BB];
__device__ unsigned g_arrive  = 0;
__device__ unsigned g_release = 0;

// ---------------------------------------------------------------------------
// Software grid barrier (all blocks co-resident by construction).
// ---------------------------------------------------------------------------
__device__ __forceinline__ void gbar(unsigned nb, unsigned& target)
{
    __syncthreads();
    if (threadIdx.x == 0) {
        __threadfence();
        unsigned old = atomicInc(&g_arrive, nb - 1);
        if (old == nb - 1) {
            atomicAdd(&g_release, 1);
        } else {
            while (*((volatile unsigned*)&g_release) < target) __nanosleep(32);
        }
        __threadfence();
    }
    target++;
    __syncthreads();
}

// ---------------------------------------------------------------------------
// Warp-per-tile reconstruction solver. Lane = column; v[32]/mask[32] in regs.
// No __syncthreads, no LDS in the iteration loop. Halo influence injected
// once (constant source; monotone max => equivalent to per-iteration use).
// ---------------------------------------------------------------------------
__device__ bool tile_warp(float* __restrict__ mk, const float* __restrict__ msk,
                          int t, float* __restrict__ buf, int lane)
{
    const int img = t >> 8, local = t & 255;
    const int x0 = (local & 15) << 5, y0 = ((local >> 4) & 15) << 5;
    float* m        = mk  + (size_t)img * IMG;
    const float* ms = msk + (size_t)img * IMG;

    // ---- stage mask 32x32 (stride 36), extract columns ----
    for (int i = lane; i < 1024; i += 32) {
        int y = i >> 5, x = i & 31;
        buf[y * 36 + x] = __ldg(&ms[(y0 + y) * WW + x0 + x]);
    }
    __syncwarp();
    float mask[32];
#pragma unroll
    for (int y = 0; y < 32; y++) mask[y] = buf[y * 36 + lane];
    __syncwarp();

    // ---- stage marker 34x34 with halo (-inf outside image) ----
    for (int i = lane; i < 34 * 34; i += 32) {
        int ly = i / 34, lx = i - ly * 34;
        int gy = y0 + ly - 1, gx = x0 + lx - 1;
        float v = NEG;
        if ((unsigned)gx < WW && (unsigned)gy < HH) v = __ldcg(&m[gy * WW + gx]);
        buf[ly * 36 + lx] = v;
    }
    __syncwarp();

    // ---- extract columns + one-shot halo injection ----
    float v[32];
    bool anych = false;
#pragma unroll
    for (int y = 0; y < 32; y++) {
        float raw = buf[(y + 1) * 36 + lane + 1];
        float c = NEG;
        if (y == 0)
            c = fmaxf(fmaxf(buf[lane], buf[lane + 1]), buf[lane + 2]);
        if (y == 31)
            c = fmaxf(c, fmaxf(fmaxf(buf[33 * 36 + lane], buf[33 * 36 + lane + 1]),
                               buf[33 * 36 + lane + 2]));
        if (lane == 0)
            c = fmaxf(c, fmaxf(fmaxf(buf[y * 36], buf[(y + 1) * 36]), buf[(y + 2) * 36]));
        if (lane == 31)
            c = fmaxf(c, fmaxf(fmaxf(buf[y * 36 + 33], buf[(y + 1) * 36 + 33]),
                               buf[(y + 2) * 36 + 33]));
        float nv = fminf(mask[y], fmaxf(raw, c));
        v[y] = nv;
        anych |= (nv > raw);
    }

    // ---- iterate: batched horizontal shuffles + vertical GS sweeps ----
    for (int it = 0; it < 40; ++it) {
        float H[32];
#pragma unroll
        for (int y = 0; y < 32; y++) {
            float t3 = v[y];
            if (y > 0)  t3 = fmaxf(t3, v[y - 1]);
            if (y < 31) t3 = fmaxf(t3, v[y + 1]);
            float L = __shfl_up_sync(0xffffffffu, t3, 1);
            float R = __shfl_down_sync(0xffffffffu, t3, 1);
            if (lane == 0)  L = NEG;
            if (lane == 31) R = NEG;
            H[y] = fmaxf(L, R);
        }
        bool ch = false;
        float a = NEG;
#pragma unroll
        for (int y = 0; y < 32; y++) {
            float cnd = fmaxf(H[y], a);
            if (y < 31) cnd = fmaxf(cnd, v[y + 1]);
            float nv = fminf(mask[y], fmaxf(v[y], cnd));
            ch |= (nv > v[y]);
            v[y] = nv;
            a = nv;
        }
        float b = NEG;
#pragma unroll
        for (int y = 31; y >= 0; y--) {
            float nv = fminf(mask[y], fmaxf(v[y], b));
            ch |= (nv > v[y]);
            v[y] = nv;
            b = nv;
        }
        anych |= ch;
        if (!__any_sync(0xffffffffu, ch)) break;
    }

    bool wany = __any_sync(0xffffffffu, anych);
    if (wany) {
        __syncwarp();
#pragma unroll
        for (int y = 0; y < 32; y++) buf[y * 36 + lane] = v[y];
        __syncwarp();
        for (int i = lane; i < 1024; i += 32)
            __stcg(&m[(y0 + (i >> 5)) * WW + x0 + (i & 31)], buf[(i >> 5) * 36 + (i & 31)]);
    }
    return wany;
}

// ---------------------------------------------------------------------------
// Reconstruction: rounds with dirty-wavefront skip + exact global early exit.
// ---------------------------------------------------------------------------
__device__ __forceinline__ void recon(
    float* mk, const float* msk, int maxr, int flagbase,
    unsigned nb, unsigned& target, float* wbuf, int lane, int gw, int nw)
{
    for (int r = 0; r < maxr; ++r) {
        const int par = r & 1;
        for (int t0 = gw; t0 < NTILES; t0 += nw) {
            int t = (r & 1) ? (NTILES - 1 - t0) : t0;   // snake across rounds
            bool need = true;
            if (r > 0) {
                bool mine = false;
                if (lane < 9) {
                    int dy = lane / 3 - 1, dx = lane % 3 - 1;
                    int tyy = (t >> 4) & 15, txx = t & 15;
                    int ny = tyy + dy, nx = txx + dx;
                    if ((unsigned)ny < 16u && (unsigned)nx < 16u)
                        mine = (*(volatile unsigned char*)&g_dirty[par ^ 1][t + dy * 16 + dx]) != 0;
                }
                need = __any_sync(0xffffffffu, mine);
            }
            bool ch = false;
            if (need) ch = tile_warp(mk, msk, t, wbuf, lane);
            if (lane == 0) {
                *(volatile unsigned char*)&g_dirty[par][t] = ch ? 1 : 0;
                if (ch) *(volatile int*)&g_chflag[flagbase + r] = 1;
            }
        }
        gbar(nb, target);
        if (*(volatile int*)&g_chflag[flagbase + r] == 0) break;  // uniform
    }
}

// ---------------------------------------------------------------------------
// The whole pipeline in one persistent kernel. 128 threads = 4 tile-warps.
// ---------------------------------------------------------------------------
__global__ void __launch_bounds__(128, 4) persistent_kernel(
    const float* __restrict__ x, const float* __restrict__ h,
    const float* __restrict__ u, float* __restrict__ out, int nbi)
{
    __shared__ float sbuf[4][34 * 36];
    __shared__ float red[4];
    const unsigned nb = (unsigned)nbi;
    const int tid = threadIdx.x;
    const int bid = blockIdx.x;
    const int lane = tid & 31;
    const int wid = tid >> 5;
    const int gid = bid * 128 + tid;
    const int nthr = nbi * 128;
    const int gw = bid * 4 + wid;
    const int nw = nbi * 4;
    float* wbuf = &sbuf[wid][0];
    unsigned target = *((volatile unsigned*)&g_release) + 1;

    // ---- P0: g_m = x - h ; reset flags/counters --------------------------
    {
        const float4* x4 = (const float4*)x;
        float4* m4 = (float4*)g_m;
        for (int i4 = gid; i4 < TOT / 4; i4 += nthr) {
            float4 v = __ldg(&x4[i4]);
            float hh = __ldg(&h[i4 >> 16]);
            v.x -= hh; v.y -= hh; v.z -= hh; v.w -= hh;
            __stcg(&m4[i4], v);
        }
        if (bid == 0) {
            if (tid < NFLAGS) __stcg(&g_chflag[tid], 0);
            if (tid < 2)      __stcg(&g_rflags[tid], 0);
            if (tid < BB)     __stcg(&g_cc[tid], 0.0f);
        }
    }
    gbar(nb, target);

    // ---- Rec1: xh = rec(x - h, x) ----------------------------------------
    recon(g_m, x, MAXR1, 0, nb, target, wbuf, lane, gw, nw);

    // ---- P1: out[16..] = xh ; g_m2 = xh - eps ----------------------------
    {
        const float4* m4 = (const float4*)g_m;
        float4* m24 = (float4*)g_m2;
        float4* o4 = (float4*)(out + 16);
        for (int i4 = gid; i4 < TOT / 4; i4 += nthr) {
            float4 v = __ldcg(&m4[i4]);
            o4[i4] = v;
            v.x -= 1e-5f; v.y -= 1e-5f; v.z -= 1e-5f; v.w -= 1e-5f;
            __stcg(&m24[i4], v);
        }
    }
    gbar(nb, target);

    // ---- Rec2: rec(xh - eps, xh) -----------------------------------------
    recon(g_m2, g_m, MAXR2, MAXR1, nb, target, wbuf, lane, gw, nw);

    // ---- P2: Rmax = (xh > rec2); M = min(u, Rmax); global min/max flags --
    {
        const float4* m4  = (const float4*)g_m;
        const float4* m24 = (const float4*)g_m2;
        const float4* u4  = (const float4*)u;
        float4* r4 = (float4*)g_rmx;
        float4* m34 = (float4*)g_m3;
        bool a0 = false, a1 = false;
        for (int i4 = gid; i4 < TOT / 4; i4 += nthr) {
            float4 a = __ldcg(&m4[i4]);
            float4 b = __ldcg(&m24[i4]);
            float4 uu = __ldg(&u4[i4]);
            float4 r, m3;
            r.x = (a.x > b.x) ? 1.0f : 0.0f;
            r.y = (a.y > b.y) ? 1.0f : 0.0f;
            r.z = (a.z > b.z) ? 1.0f : 0.0f;
            r.w = (a.w > b.w) ? 1.0f : 0.0f;
            if (r.x == 0.f || r.y == 0.f || r.z == 0.f || r.w == 0.f) a0 = true;
            if (r.x == 1.f || r.y == 1.f || r.z == 1.f || r.w == 1.f) a1 = true;
            m3.x = fminf(uu.x, r.x); m3.y = fminf(uu.y, r.y);
            m3.z = fminf(uu.z, r.z); m3.w = fminf(uu.w, r.w);
            __stcg(&r4[i4], r);
            __stcg(&m34[i4], m3);
        }
        bool b0 = __syncthreads_or(a0);
        bool b1 = __syncthreads_or(a1);
        if (tid == 0) {
            if (b0) *(volatile int*)&g_rflags[0] = 1;
            if (b1) *(volatile int*)&g_rflags[1] = 1;
        }
    }
    gbar(nb, target);

    // ---- Rec3: R = rec(M, Rmax) ------------------------------------------
    recon(g_m3, g_rmx, MAXR3, MAXR1 + MAXR2, nb, target, wbuf, lane, gw, nw);

    // ---- P3: CC[img] = sum(u == R) ---------------------------------------
    {
        for (int t = bid; t < NTILES; t += nbi) {
            int img = t >> 8, local = t & 255;
            int x0 = (local & 15) << 5, y0 = ((local >> 4) & 15) << 5;
            const float* uu = u + (size_t)img * IMG;
            const float* m3 = g_m3 + (size_t)img * IMG;
            float s = 0.0f;
#pragma unroll
            for (int k = 0; k < 8; k++) {
                int idx = (y0 + wid * 8 + k) * WW + x0 + lane;
                s += (__ldg(&uu[idx]) == __ldcg(&m3[idx])) ? 1.0f : 0.0f;
            }
#pragma unroll
            for (int off = 16; off; off >>= 1)
                s += __shfl_down_sync(0xffffffffu, s, off);
            if (lane == 0) red[wid] = s;
            __syncthreads();
            if (tid == 0)
                atomicAdd(&g_cc[img], red[0] + red[1] + red[2] + red[3]);
            __syncthreads();
        }
    }
    gbar(nb, target);

    // ---- P4: CC_ ---------------------------------------------------------
    if (bid == 0 && tid < BB) {
        float maxR = (*(volatile int*)&g_rflags[1]) ? 1.0f : 0.0f;
        float minR = (*(volatile int*)&g_rflags[0]) ? 0.0f : 1.0f;
        float diff = maxR - minR;
        float cc = *(volatile float*)&g_cc[tid];
        out[tid] = fminf(cc, 100.0f * diff * cc);
    }
}

// ---------------------------------------------------------------------------
extern "C" void kernel_launch(void* const* d_in, const int* in_sizes, int n_in,
                              void* d_out, int out_size)
{
    // Identify inputs by size (x and u are 4194304, h is 16; x precedes u)
    const float *x = nullptr, *h = nullptr, *u = nullptr;
    for (int i = 0; i < n_in; i++) {
        if (in_sizes[i] == BB) h = (const float*)d_in[i];
        else if (!x)           x = (const float*)d_in[i];
        else                   u = (const float*)d_in[i];
    }
    float* out = (float*)d_out;

    int dev = 0, sms = 0, occ = 0;
    cudaGetDevice(&dev);
    cudaDeviceGetAttribute(&sms, cudaDevAttrMultiProcessorCount, dev);
    cudaOccupancyMaxActiveBlocksPerMultiprocessor(&occ, persistent_kernel, 128, 0);
    int nb = sms * occ;
    if (nb <= 0) nb = 256;       // conservative fallback, guaranteed resident
    if (nb > 2048) nb = 2048;

    persistent_kernel<<<nb, 128>>>(x, h, u, out, nb);
}

// round 4
// speedup vs baseline: 1.6263x; 1.6263x over previous
#include <cuda_runtime.h>
#include <math.h>

#define HH 512
#define WW 512
#define BB 16
#define IMG (HH*WW)            // 262144 = 1<<18
#define TOT (BB*IMG)           // 4194304
#define NTILES 4096            // 16 x-tiles * 16 y-tiles * 16 images
#define MAXR1 28
#define MAXR2 28
#define MAXR3 16
#define NFLAGS (MAXR1+MAXR2+MAXR3)
#define NEG (-INFINITY)

// Scratch (static __device__ arrays: allocation-free)
__device__ float g_m  [TOT];
__device__ float g_m2 [TOT];
__device__ float g_rmx[TOT];
__device__ float g_m3 [TOT];
__device__ unsigned char g_dirty[2][NTILES];
__device__ int   g_chflag[NFLAGS];
__device__ int   g_rflags[2];          // [0]: any Rmax==0, [1]: any Rmax==1
__device__ float g_cc[BB];
__device__ unsigned g_arrive  = 0;
__device__ unsigned g_release = 0;

// ---------------------------------------------------------------------------
// Software grid barrier (all blocks co-resident by construction).
// ---------------------------------------------------------------------------
__device__ __forceinline__ void gbar(unsigned nb, unsigned& target)
{
    __syncthreads();
    if (threadIdx.x == 0) {
        __threadfence();
        unsigned old = atomicInc(&g_arrive, nb - 1);
        if (old == nb - 1) {
            atomicAdd(&g_release, 1);
        } else {
            while (*((volatile unsigned*)&g_release) < target) __nanosleep(32);
        }
        __threadfence();
    }
    target++;
    __syncthreads();
}

// ---------------------------------------------------------------------------
// Block-per-tile chaotic Gauss-Seidel relaxation.
// Thread (tx,ty) owns 4 CONTIGUOUS rows 4*ty..4*ty+3 of column tx.
// Down sweep uses freshly updated cur[k-1] (>=4px vertical / iter), up sweep
// register-only. In-place smem updates, ONE sync per iteration. Races are
// benign (monotone max-lattice); "no increase in a full pass" is an exact
// fixpoint test.
// ---------------------------------------------------------------------------
__device__ __forceinline__ bool process_tile(
    float* __restrict__ mk, const float* __restrict__ msk,
    int img, int x0, int y0, float (*sm)[34], int tid)
{
    float* m        = mk  + (size_t)img * IMG;
    const float* ms = msk + (size_t)img * IMG;
    const int ty = tid >> 5, tx = tid & 31;          // ty 0..7, tx 0..31
    const int sy = tid >> 3, sxs = (tid & 7) << 2;   // staging: row, 4-col seg

    // ---- stage interior 32x32 (float4, 32-aligned) ----
    {
        float4 v = __ldcg((const float4*)&m[(y0 + sy) * WW + x0 + sxs]);
        sm[sy + 1][sxs + 1] = v.x;
        sm[sy + 1][sxs + 2] = v.y;
        sm[sy + 1][sxs + 3] = v.z;
        sm[sy + 1][sxs + 4] = v.w;
    }
    // ---- halo (132 cells, -inf outside image) ----
    if (tid < 132) {
        int ly, lx, gy, gx;
        if (tid < 34)        { ly = 0;        lx = tid;       gy = y0 - 1;         gx = x0 + tid - 1;  }
        else if (tid < 68)   { ly = 33;       lx = tid - 34;  gy = y0 + 32;        gx = x0 + tid - 35; }
        else if (tid < 100)  { ly = tid - 67; lx = 0;         gy = y0 + tid - 68;  gx = x0 - 1;        }
        else                 { ly = tid - 99; lx = 33;        gy = y0 + tid - 100; gx = x0 + 32;       }
        float v = NEG;
        if ((unsigned)gx < WW && (unsigned)gy < HH) v = __ldcg(&m[gy * WW + gx]);
        sm[ly][lx] = v;
    }

    float mval[4], cur[4];
#pragma unroll
    for (int k = 0; k < 4; k++)
        mval[k] = __ldg(&ms[(y0 + 4 * ty + k) * WW + x0 + tx]);
    __syncthreads();
#pragma unroll
    for (int k = 0; k < 4; k++)
        cur[k] = sm[4 * ty + k + 1][tx + 1];

    bool any = false;
    for (int it = 0; it < 48; ++it) {
        bool ch = false;
        // down sweep (GS vertical via registers; horizontal/diag via live smem)
#pragma unroll
        for (int k = 0; k < 4; k++) {
            const int r = 4 * ty + k;                     // smem row of up-nbrs
            float up_c = (k > 0) ? cur[k - 1] : sm[r][tx + 1];
            float dn_c = (k < 3) ? cur[k + 1] : sm[r + 2][tx + 1];
            float c = fmaxf(fmaxf(sm[r][tx], up_c), sm[r][tx + 2]);
            c = fmaxf(c, fmaxf(sm[r + 1][tx], sm[r + 1][tx + 2]));
            c = fmaxf(c, fmaxf(fmaxf(sm[r + 2][tx], dn_c), sm[r + 2][tx + 2]));
            float nv = fminf(mval[k], fmaxf(cur[k], c));
            if (nv > cur[k]) { cur[k] = nv; sm[r + 1][tx + 1] = nv; ch = true; }
        }
        // up sweep (register-only vertical back-propagation)
#pragma unroll
        for (int k = 2; k >= 0; k--) {
            float nv = fminf(mval[k], fmaxf(cur[k], cur[k + 1]));
            if (nv > cur[k]) { cur[k] = nv; sm[4 * ty + k + 1][tx + 1] = nv; ch = true; }
        }
        any |= ch;
        if (!__syncthreads_or(ch)) break;
    }

    bool blkany = __syncthreads_or(any);
    if (blkany) {
        float4 v;
        v.x = sm[sy + 1][sxs + 1];
        v.y = sm[sy + 1][sxs + 2];
        v.z = sm[sy + 1][sxs + 3];
        v.w = sm[sy + 1][sxs + 4];
        __stcg((float4*)&m[(y0 + sy) * WW + x0 + sxs], v);
    }
    return blkany;
}

// ---------------------------------------------------------------------------
// Reconstruction: rounds of tile relaxation with dirty-skip + exact early exit.
// ---------------------------------------------------------------------------
__device__ __forceinline__ void recon(
    float* mk, const float* msk, int maxr, int flagbase,
    unsigned nb, unsigned& target, float (*sm)[34], int tid, int bid)
{
    for (int r = 0; r < maxr; ++r) {
        const int par = r & 1;
        for (int t = bid; t < NTILES; t += (int)nb) {
            bool need = true;
            if (r > 0) {
                bool mine = false;
                if (tid < 9) {
                    int dy = tid / 3 - 1, dx = tid % 3 - 1;
                    int tyy = (t >> 4) & 15, txx = t & 15;
                    int ny = tyy + dy, nx = txx + dx;
                    if ((unsigned)ny < 16u && (unsigned)nx < 16u)
                        mine = (*(volatile unsigned char*)&g_dirty[par ^ 1][t + dy * 16 + dx]) != 0;
                }
                need = __syncthreads_or(mine);
            }
            bool ch = false;
            if (need) {
                int img = t >> 8, local = t & 255;
                ch = process_tile(mk, msk, img, (local & 15) << 5, ((local >> 4) & 15) << 5, sm, tid);
            }
            if (tid == 0) {
                *(volatile unsigned char*)&g_dirty[par][t] = ch ? 1 : 0;
                if (ch) *(volatile int*)&g_chflag[flagbase + r] = 1;
            }
            __syncthreads();
        }
        gbar(nb, target);
        if (*(volatile int*)&g_chflag[flagbase + r] == 0) break;  // uniform
    }
}

// ---------------------------------------------------------------------------
// The whole pipeline in one persistent kernel.
// ---------------------------------------------------------------------------
__global__ void __launch_bounds__(256) persistent_kernel(
    const float* __restrict__ x, const float* __restrict__ h,
    const float* __restrict__ u, float* __restrict__ out, int nbi)
{
    __shared__ float sm[34][34];
    __shared__ float red[8];
    const unsigned nb = (unsigned)nbi;
    const int tid = threadIdx.x;
    const int bid = blockIdx.x;
    const int gid = bid * 256 + tid;
    const int nthr = nbi * 256;
    unsigned target = *((volatile unsigned*)&g_release) + 1;

    // ---- P0: g_m = x - h ; reset flags/counters --------------------------
    {
        const float4* x4 = (const float4*)x;
        float4* m4 = (float4*)g_m;
        for (int i4 = gid; i4 < TOT / 4; i4 += nthr) {
            float4 v = __ldg(&x4[i4]);
            float hh = __ldg(&h[i4 >> 16]);
            v.x -= hh; v.y -= hh; v.z -= hh; v.w -= hh;
            __stcg(&m4[i4], v);
        }
        if (bid == 0) {
            if (tid < NFLAGS) __stcg(&g_chflag[tid], 0);
            if (tid < 2)      __stcg(&g_rflags[tid], 0);
            if (tid < BB)     __stcg(&g_cc[tid], 0.0f);
        }
    }
    gbar(nb, target);

    // ---- Rec1: xh = rec(x - h, x) ----------------------------------------
    recon(g_m, x, MAXR1, 0, nb, target, sm, tid, bid);

    // ---- P1: out[16..] = xh ; g_m2 = xh - eps ----------------------------
    {
        const float4* m4 = (const float4*)g_m;
        float4* m24 = (float4*)g_m2;
        float4* o4 = (float4*)(out + 16);
        for (int i4 = gid; i4 < TOT / 4; i4 += nthr) {
            float4 v = __ldcg(&m4[i4]);
            o4[i4] = v;
            v.x -= 1e-5f; v.y -= 1e-5f; v.z -= 1e-5f; v.w -= 1e-5f;
            __stcg(&m24[i4], v);
        }
    }
    gbar(nb, target);

    // ---- Rec2: rec(xh - eps, xh) -----------------------------------------
    recon(g_m2, g_m, MAXR2, MAXR1, nb, target, sm, tid, bid);

    // ---- P2: Rmax = (xh > rec2); M = min(u, Rmax); global min/max flags --
    {
        const float4* m4  = (const float4*)g_m;
        const float4* m24 = (const float4*)g_m2;
        const float4* u4  = (const float4*)u;
        float4* r4 = (float4*)g_rmx;
        float4* m34 = (float4*)g_m3;
        bool a0 = false, a1 = false;
        for (int i4 = gid; i4 < TOT / 4; i4 += nthr) {
            float4 a = __ldcg(&m4[i4]);
            float4 b = __ldcg(&m24[i4]);
            float4 uu = __ldg(&u4[i4]);
            float4 r, m3;
            r.x = (a.x > b.x) ? 1.0f : 0.0f;
            r.y = (a.y > b.y) ? 1.0f : 0.0f;
            r.z = (a.z > b.z) ? 1.0f : 0.0f;
            r.w = (a.w > b.w) ? 1.0f : 0.0f;
            if (r.x == 0.f || r.y == 0.f || r.z == 0.f || r.w == 0.f) a0 = true;
            if (r.x == 1.f || r.y == 1.f || r.z == 1.f || r.w == 1.f) a1 = true;
            m3.x = fminf(uu.x, r.x); m3.y = fminf(uu.y, r.y);
            m3.z = fminf(uu.z, r.z); m3.w = fminf(uu.w, r.w);
            __stcg(&r4[i4], r);
            __stcg(&m34[i4], m3);
        }
        bool b0 = __syncthreads_or(a0);
        bool b1 = __syncthreads_or(a1);
        if (tid == 0) {
            if (b0) *(volatile int*)&g_rflags[0] = 1;
            if (b1) *(volatile int*)&g_rflags[1] = 1;
        }
    }
    gbar(nb, target);

    // ---- Rec3: R = rec(M, Rmax) ------------------------------------------
    recon(g_m3, g_rmx, MAXR3, MAXR1 + MAXR2, nb, target, sm, tid, bid);

    // ---- P3: CC[img] = sum(u == R) ---------------------------------------
    {
        const int ty = tid >> 5, tx = tid & 31;
        for (int t = bid; t < NTILES; t += nbi) {
            int img = t >> 8, local = t & 255;
            int x0 = (local & 15) << 5, y0 = ((local >> 4) & 15) << 5;
            const float* uu = u + (size_t)img * IMG;
            const float* m3 = g_m3 + (size_t)img * IMG;
            float s = 0.0f;
#pragma unroll
            for (int k = 0; k < 4; k++) {
                int idx = (y0 + ty + 8 * k) * WW + x0 + tx;
                s += (__ldg(&uu[idx]) == __ldcg(&m3[idx])) ? 1.0f : 0.0f;
            }
#pragma unroll
            for (int off = 16; off; off >>= 1)
                s += __shfl_down_sync(0xffffffffu, s, off);
            if ((tid & 31) == 0) red[tid >> 5] = s;
            __syncthreads();
            if (tid == 0) {
                float tot = 0.0f;
#pragma unroll
                for (int w = 0; w < 8; w++) tot += red[w];
                atomicAdd(&g_cc[img], tot);
            }
            __syncthreads();
        }
    }
    gbar(nb, target);

    // ---- P4: CC_ ---------------------------------------------------------
    if (bid == 0 && tid < BB) {
        float maxR = (*(volatile int*)&g_rflags[1]) ? 1.0f : 0.0f;
        float minR = (*(volatile int*)&g_rflags[0]) ? 0.0f : 1.0f;
        float diff = maxR - minR;
        float cc = *(volatile float*)&g_cc[tid];
        out[tid] = fminf(cc, 100.0f * diff * cc);
    }
}

// ---------------------------------------------------------------------------
extern "C" void kernel_launch(void* const* d_in, const int* in_sizes, int n_in,
                              void* d_out, int out_size)
{
    // Identify inputs by size (x and u are 4194304, h is 16; x precedes u)
    const float *x = nullptr, *h = nullptr, *u = nullptr;
    for (int i = 0; i < n_in; i++) {
        if (in_sizes[i] == BB) h = (const float*)d_in[i];
        else if (!x)           x = (const float*)d_in[i];
        else                   u = (const float*)d_in[i];
    }
    float* out = (float*)d_out;

    int dev = 0, sms = 0, occ = 0;
    cudaGetDevice(&dev);
    cudaDeviceGetAttribute(&sms, cudaDevAttrMultiProcessorCount, dev);
    cudaOccupancyMaxActiveBlocksPerMultiprocessor(&occ, persistent_kernel, 256, 0);
    int nb = sms * occ;
    if (nb <= 0) nb = 256;       // conservative fallback, guaranteed resident
    if (nb > 2048) nb = 2048;

    persistent_kernel<<<nb, 256>>>(x, h, u, out, nb);
}